// round 1
// baseline (speedup 1.0000x reference)
#include <cuda_runtime.h>

// ort = mean(x1 @ x2^T) = dot(colsum(x1), colsum(x2)) / N^2
// N = 8192 rows, D = 1024 cols. Pure HBM-bound streaming reduction: 64 MB read.

#define D 1024

__device__ float g_colsum[2 * D];

__global__ void zero_kernel() {
    int i = blockIdx.x * blockDim.x + threadIdx.x;
    if (i < 2 * D) g_colsum[i] = 0.0f;
}

__global__ void colsum_kernel(const float4* __restrict__ x1,
                              const float4* __restrict__ x2,
                              int nrows) {
    const float4* x = (blockIdx.y == 0) ? x1 : x2;
    float* out = g_colsum + blockIdx.y * D;

    const int c = threadIdx.x;          // 0..255, owns columns [4c, 4c+4)
    float4 acc = make_float4(0.f, 0.f, 0.f, 0.f);

    // Grid-strided over rows; loads in consecutive iterations are independent
    // (acc is the only carried dep, and it's FMA-latency-hidden), so ptxas
    // front-batches them -> high MLP, DRAM-limited.
    #pragma unroll 4
    for (int r = blockIdx.x; r < nrows; r += gridDim.x) {
        float4 v = __ldg(&x[(size_t)r * (D / 4) + c]);
        acc.x += v.x;
        acc.y += v.y;
        acc.z += v.z;
        acc.w += v.w;
    }

    atomicAdd(&out[4 * c + 0], acc.x);
    atomicAdd(&out[4 * c + 1], acc.y);
    atomicAdd(&out[4 * c + 2], acc.z);
    atomicAdd(&out[4 * c + 3], acc.w);
}

__global__ void dot_kernel(float* __restrict__ out, double inv_n2) {
    __shared__ double sred[32];
    const int t = threadIdx.x;           // 1024 threads

    double v = (double)g_colsum[t] * (double)g_colsum[D + t];

    // warp reduce
    #pragma unroll
    for (int o = 16; o > 0; o >>= 1)
        v += __shfl_down_sync(0xffffffffu, v, o);
    if ((t & 31) == 0) sred[t >> 5] = v;
    __syncthreads();

    if (t < 32) {
        double w = (t < (int)(blockDim.x >> 5)) ? sred[t] : 0.0;
        #pragma unroll
        for (int o = 16; o > 0; o >>= 1)
            w += __shfl_down_sync(0xffffffffu, w, o);
        if (t == 0) out[0] = (float)(w * inv_n2);
    }
}

extern "C" void kernel_launch(void* const* d_in, const int* in_sizes, int n_in,
                              void* d_out, int out_size) {
    const float4* x1 = (const float4*)d_in[0];
    const float4* x2 = (const float4*)d_in[1];
    float* out = (float*)d_out;

    const int nrows = in_sizes[0] / D;   // 8192
    const double inv_n2 = 1.0 / ((double)nrows * (double)nrows);

    // Must re-zero the device-global accumulator on every (graph-replayed) call.
    zero_kernel<<<2, 1024>>>();

    // 512 row-stripe blocks x {x1, x2}; 256 threads each (one float4 per thread
    // per row). ~7 blocks/SM on 148 SMs -> enough parallelism to saturate HBM.
    colsum_kernel<<<dim3(512, 2), 256>>>(x1, x2, nrows);

    dot_kernel<<<1, 1024>>>(out, inv_n2);
}

// round 6
// speedup vs baseline: 1.7295x; 1.7295x over previous
#include <cuda_runtime.h>

// ort = mean(x1 @ x2^T) = dot(colsum(x1), colsum(x2)) / N^2
// N = 8192 rows, D = 1024 cols. 64 MB read, pure HBM-bound.
// Single fused kernel: colsum-atomics + fence-counter last-block finish.
// Device globals are zero-init at load; the last block restores them to zero
// before exit, so state is invariant across CUDA-graph replays.

#define D 1024
#define GRID 296
#define TPB 256

__device__ float g_colsum[2 * D];        // zero-initialized; invariant
__device__ unsigned int g_done = 0;      // completion counter; invariant

__global__ __launch_bounds__(TPB) void fused_kernel(
    const float4* __restrict__ x1,
    const float4* __restrict__ x2,
    float* __restrict__ out,
    int nrows, double inv_n2) {

    const int c = threadIdx.x;           // owns cols [4c, 4c+4) of both inputs

    // Contiguous row stripe per block: sequential 4KB lines, ideal DRAM locality.
    const int per = (nrows + GRID - 1) / GRID;       // 28 for 8192/296
    const int r0 = blockIdx.x * per;
    const int r1 = min(r0 + per, nrows);

    float4 a1 = make_float4(0.f, 0.f, 0.f, 0.f);
    float4 a2 = make_float4(0.f, 0.f, 0.f, 0.f);

    // Two independent 16B loads per iteration + deep unroll -> high MLP.
    #pragma unroll 7
    for (int r = r0; r < r1; r++) {
        float4 v1 = __ldg(&x1[(size_t)r * (D / 4) + c]);
        float4 v2 = __ldg(&x2[(size_t)r * (D / 4) + c]);
        a1.x += v1.x; a1.y += v1.y; a1.z += v1.z; a1.w += v1.w;
        a2.x += v2.x; a2.y += v2.y; a2.z += v2.z; a2.w += v2.w;
    }

    float* o1 = g_colsum;
    float* o2 = g_colsum + D;
    atomicAdd(&o1[4 * c + 0], a1.x);
    atomicAdd(&o1[4 * c + 1], a1.y);
    atomicAdd(&o1[4 * c + 2], a1.z);
    atomicAdd(&o1[4 * c + 3], a1.w);
    atomicAdd(&o2[4 * c + 0], a2.x);
    atomicAdd(&o2[4 * c + 1], a2.y);
    atomicAdd(&o2[4 * c + 2], a2.z);
    atomicAdd(&o2[4 * c + 3], a2.w);

    // Completion protocol: last block finishes the reduction.
    __shared__ bool s_last;
    __threadfence();
    __syncthreads();
    if (threadIdx.x == 0)
        s_last = (atomicAdd(&g_done, 1u) == GRID - 1);
    __syncthreads();
    if (!s_last) return;

    // ---- last block only: dot(colsum1, colsum2) / N^2 ----
    double v = 0.0;
    #pragma unroll
    for (int i = 0; i < 4; i++) {
        int idx = 4 * c + i;
        v += (double)g_colsum[idx] * (double)g_colsum[D + idx];
    }

    __shared__ double sred[TPB / 32];
    #pragma unroll
    for (int o = 16; o > 0; o >>= 1)
        v += __shfl_down_sync(0xffffffffu, v, o);
    if ((c & 31) == 0) sred[c >> 5] = v;
    __syncthreads();
    if (c < 32) {
        double w = (c < TPB / 32) ? sred[c] : 0.0;
        #pragma unroll
        for (int o = 4; o > 0; o >>= 1)
            w += __shfl_down_sync(0xffffffffu, w, o);
        if (c == 0) out[0] = (float)(w * inv_n2);
    }

    // Restore invariants for the next graph replay.
    #pragma unroll
    for (int i = 0; i < 4; i++) {
        g_colsum[4 * c + i] = 0.0f;
        g_colsum[D + 4 * c + i] = 0.0f;
    }
    if (c == 0) g_done = 0u;
}

extern "C" void kernel_launch(void* const* d_in, const int* in_sizes, int n_in,
                              void* d_out, int out_size) {
    const float4* x1 = (const float4*)d_in[0];
    const float4* x2 = (const float4*)d_in[1];
    float* out = (float*)d_out;

    const int nrows = in_sizes[0] / D;   // 8192
    const double inv_n2 = 1.0 / ((double)nrows * (double)nrows);

    fused_kernel<<<GRID, TPB>>>(x1, x2, out, nrows, inv_n2);
}

// round 7
// speedup vs baseline: 2.6716x; 1.5448x over previous
#include <cuda_runtime.h>

// ort = mean(x1 @ x2^T) = dot(colsum(x1), colsum(x2)) / N^2
// N = 8192 rows, D = 1024 cols. 64 MB read, pure HBM-bound.
// Single fused kernel. 1024-thread blocks = 4 row-groups x 256 col-threads:
// full 64-warp occupancy at GRID=296 (2 CTAs/SM) for deep MLP, smem-reduce
// across row-groups so the global atomic count stays at 296 x 2048.
// Device globals are zero-init at load; the last block restores them to zero
// before exit, so state is invariant across CUDA-graph replays.

#define D 1024
#define GRID 296
#define TPB 1024

__device__ float g_colsum[2 * D];        // zero-initialized; invariant
__device__ unsigned int g_done = 0;      // completion counter; invariant

__global__ __launch_bounds__(TPB, 2) void fused_kernel(
    const float4* __restrict__ x1,
    const float4* __restrict__ x2,
    float* __restrict__ out,
    int nrows, double inv_n2) {

    const int t = threadIdx.x;
    const int g = t >> 8;                // row group 0..3
    const int c = t & 255;               // col-thread: owns cols [4c, 4c+4)

    // Contiguous 28-row stripe per block; group g takes rows g, g+4, ...
    const int per = (nrows + GRID - 1) / GRID;       // 28
    const int r0 = blockIdx.x * per;
    const int r1 = min(r0 + per, nrows);

    float4 a1 = make_float4(0.f, 0.f, 0.f, 0.f);
    float4 a2 = make_float4(0.f, 0.f, 0.f, 0.f);

    #pragma unroll 7
    for (int r = r0 + g; r < r1; r += 4) {
        float4 v1 = __ldg(&x1[(size_t)r * (D / 4) + c]);
        float4 v2 = __ldg(&x2[(size_t)r * (D / 4) + c]);
        a1.x += v1.x; a1.y += v1.y; a1.z += v1.z; a1.w += v1.w;
        a2.x += v2.x; a2.y += v2.y; a2.z += v2.z; a2.w += v2.w;
    }

    // ---- smem reduce across the 4 row-groups, then one atomic per column ----
    __shared__ float s[4 * D];           // 16 KB

    s[g * D + 4 * c + 0] = a1.x;
    s[g * D + 4 * c + 1] = a1.y;
    s[g * D + 4 * c + 2] = a1.z;
    s[g * D + 4 * c + 3] = a1.w;
    __syncthreads();
    {
        float v = s[t & (D - 1)] + s[D + (t & (D - 1))]
                + s[2 * D + (t & (D - 1))] + s[3 * D + (t & (D - 1))];
        atomicAdd(&g_colsum[t & (D - 1)], v);
    }
    __syncthreads();
    s[g * D + 4 * c + 0] = a2.x;
    s[g * D + 4 * c + 1] = a2.y;
    s[g * D + 4 * c + 2] = a2.z;
    s[g * D + 4 * c + 3] = a2.w;
    __syncthreads();
    {
        float v = s[t & (D - 1)] + s[D + (t & (D - 1))]
                + s[2 * D + (t & (D - 1))] + s[3 * D + (t & (D - 1))];
        atomicAdd(&g_colsum[D + (t & (D - 1))], v);
    }

    // Completion protocol: last block finishes the reduction.
    __shared__ bool s_last;
    __threadfence();
    __syncthreads();
    if (t == 0)
        s_last = (atomicAdd(&g_done, 1u) == GRID - 1);
    __syncthreads();
    if (!s_last) return;

    // ---- last block only: dot(colsum1, colsum2) / N^2 ----
    double v = (double)g_colsum[t] * (double)g_colsum[D + t];

    __shared__ double sred[TPB / 32];
    #pragma unroll
    for (int o = 16; o > 0; o >>= 1)
        v += __shfl_down_sync(0xffffffffu, v, o);
    if ((t & 31) == 0) sred[t >> 5] = v;
    __syncthreads();
    if (t < 32) {
        double w = sred[t];              // TPB/32 == 32 exactly
        #pragma unroll
        for (int o = 16; o > 0; o >>= 1)
            w += __shfl_down_sync(0xffffffffu, w, o);
        if (t == 0) out[0] = (float)(w * inv_n2);
    }

    // Restore invariants for the next graph replay.
    g_colsum[t] = 0.0f;
    g_colsum[D + t] = 0.0f;
    if (t == 0) g_done = 0u;
}

extern "C" void kernel_launch(void* const* d_in, const int* in_sizes, int n_in,
                              void* d_out, int out_size) {
    const float4* x1 = (const float4*)d_in[0];
    const float4* x2 = (const float4*)d_in[1];
    float* out = (float*)d_out;

    const int nrows = in_sizes[0] / D;   // 8192
    const double inv_n2 = 1.0 / ((double)nrows * (double)nrows);

    fused_kernel<<<GRID, TPB>>>(x1, x2, out, nrows, inv_n2);
}